// round 8
// baseline (speedup 1.0000x reference)
#include <cuda_runtime.h>
#include <cuda_fp16.h>
#include <math.h>
#include <stdint.h>

#define B_   64
#define N_   196
#define C_   768
#define H_   12
#define HD_  64
#define TOPK_ 16
#define HID_ 3072
#define M_   (B_ * N_)          // 12544
#define SCALE_ 0.125f
#define EPS_ 1e-5f

// ---------------- scratch (device globals) ----------------
__device__ __half g_h_h  [(size_t)M_ * C_];
__device__ __half g_qk_h [(size_t)M_ * 2 * C_];
__device__ __half g_a_h  [(size_t)M_ * H_ * TOPK_];
__device__ float  g_x1   [(size_t)M_ * C_];
__device__ __half g_hid_h[(size_t)M_ * HID_];
// fp16 weights
__device__ __half g_qkw_h[(size_t)2 * C_ * C_];
__device__ __half g_pw_h [(size_t)C_ * H_ * TOPK_];
__device__ __half g_f1w_h[(size_t)HID_ * C_];
__device__ __half g_f2w_h[(size_t)C_ * HID_];

// ---------------- helpers ----------------
__device__ __forceinline__ void cp_async16(void* smem, const void* gmem) {
    uint32_t s = (uint32_t)__cvta_generic_to_shared(smem);
    asm volatile("cp.async.cg.shared.global [%0], [%1], 16;\n" :: "r"(s), "l"(gmem));
}
__device__ __forceinline__ void cp_commit() { asm volatile("cp.async.commit_group;\n"); }
template <int Np>
__device__ __forceinline__ void cp_wait() { asm volatile("cp.async.wait_group %0;\n" :: "n"(Np) : "memory"); }
__device__ __forceinline__ void ldsm4(uint32_t& r0, uint32_t& r1, uint32_t& r2, uint32_t& r3,
                                      uint32_t addr) {
    asm volatile("ldmatrix.sync.aligned.m8n8.x4.shared.b16 {%0,%1,%2,%3}, [%4];\n"
                 : "=r"(r0), "=r"(r1), "=r"(r2), "=r"(r3) : "r"(addr));
}

// ---------------- weight fp32 -> fp16 ----------------
__global__ void cvt_kernel(const float* __restrict__ src, __half* __restrict__ dst, int n) {
    int i = (blockIdx.x * 256 + threadIdx.x) * 2;
    if (i < n) {
        float2 v = *(const float2*)&src[i];
        *(__half2*)&dst[i] = __floats2half2_rn(v.x, v.y);
    }
}

// ---------------- LayerNorm -> fp16 ----------------
__global__ void ln_kernel(const float* __restrict__ x, const float* __restrict__ g,
                          const float* __restrict__ b, __half* __restrict__ out) {
    int row = blockIdx.x;
    const float* xr = x + (size_t)row * C_;
    int tid = threadIdx.x, lane = tid & 31, warp = tid >> 5;

    float s = 0.f, s2 = 0.f;
    for (int i = tid; i < C_; i += blockDim.x) { float v = xr[i]; s += v; s2 += v * v; }
    #pragma unroll
    for (int o = 16; o > 0; o >>= 1) {
        s  += __shfl_xor_sync(0xffffffffu, s,  o);
        s2 += __shfl_xor_sync(0xffffffffu, s2, o);
    }
    __shared__ float shs[8], shs2[8], sh_mu, sh_inv;
    if (lane == 0) { shs[warp] = s; shs2[warp] = s2; }
    __syncthreads();
    if (tid == 0) {
        float ts = 0.f, ts2 = 0.f;
        #pragma unroll
        for (int w = 0; w < 8; w++) { ts += shs[w]; ts2 += shs2[w]; }
        float mu = ts / C_;
        sh_mu = mu; sh_inv = rsqrtf(ts2 / C_ - mu * mu + EPS_);
    }
    __syncthreads();
    float mu = sh_mu, inv = sh_inv;
    for (int i = tid; i < C_; i += blockDim.x) {
        float v = (xr[i] - mu) * inv * g[i] + b[i];
        out[(size_t)row * C_ + i] = __float2half(v);
    }
}

// ---------------- FP16 mma.sync GEMM (BM=128, BN=256) ----------------
// out[M,Nout] = A[M,K] @ W[Nout,K]^T (+bias)(gelu)(+res), fp32 accumulate.
// BK=64 (128B fp16 rows). 256 threads = 8 warps (2x4), warp tile 64x64.
// 3-stage cp.async, SW128 swizzle, ldmatrix.x4, m16n8k16.
#define A_TILE 16384              // 128 rows * 128 B
#define STG_B 49152               // (128 + 256) rows * 128 B
#define NSTG  3
#define SMEM_SZ (NSTG * STG_B)    // 147456

template <bool BIAS, bool GELU, bool RES, bool OUTH>
__global__ __launch_bounds__(256, 1) void gemm_h(
        const __half* __restrict__ A, const __half* __restrict__ W,
        const float* __restrict__ bias, const float* __restrict__ res,
        float* __restrict__ outf, __half* __restrict__ outh, int Nout, int K) {
    extern __shared__ char smem[];
    uint32_t sb = (uint32_t)__cvta_generic_to_shared(smem);

    int tid = threadIdx.x;
    int lane = tid & 31, wid = tid >> 5;
    int wr = wid >> 2, wc = wid & 3;          // 2x4 warp grid
    int g = lane >> 2, t = lane & 3;
    int grp = lane >> 3, l7 = lane & 7;
    int bm = blockIdx.y * 128, bn = blockIdx.x * 256;

    const __half* Ablk = A + (size_t)bm * K;
    const __half* Wblk = W + (size_t)bn * K;

    float c[4][8][4];
    #pragma unroll
    for (int i = 0; i < 4; i++)
        #pragma unroll
        for (int j = 0; j < 8; j++)
            #pragma unroll
            for (int r = 0; r < 4; r++) c[i][j][r] = 0.f;

    // loader: (128 A + 256 B) rows x 8 segs = 3072 16B tasks / 256 threads = 12
    int lrow0 = tid >> 3;         // 0..31
    int lseg  = tid & 7;
    uint32_t lcol = (uint32_t)((lseg ^ (lrow0 & 7)) << 4);
    auto load_stage = [&](int slot, int k0) {
        char* sbase = smem + slot * STG_B;
        #pragma unroll
        for (int i = 0; i < 4; i++) {         // A: 4 x 32 rows
            int row = lrow0 + i * 32;
            cp_async16(sbase + row * 128 + lcol, Ablk + (size_t)row * K + k0 + lseg * 8);
        }
        #pragma unroll
        for (int i = 0; i < 8; i++) {         // B: 8 x 32 rows
            int row = lrow0 + i * 32;
            cp_async16(sbase + A_TILE + row * 128 + lcol, Wblk + (size_t)row * K + k0 + lseg * 8);
        }
        cp_commit();
    };

    int NK = K / 64;
    load_stage(0, 0);
    load_stage(1, 64);

    int rowoffA = (grp & 1) * 8, segoffA = grp >> 1;
    int rowoffB = (grp >> 1) * 8, segoffB = grp & 1;

    for (int kc = 0; kc < NK; kc++) {
        int slot = kc % NSTG;
        cp_wait<1>();
        __syncthreads();

        if (kc + 2 < NK) load_stage((kc + 2) % NSTG, (kc + 2) * 64);
        else cp_commit();

        uint32_t sA = sb + slot * STG_B;
        uint32_t sB = sA + A_TILE;

        #pragma unroll
        for (int j = 0; j < 4; j++) {         // 4 k16-steps in BK=64
            uint32_t a[4][4], b[8][2];
            #pragma unroll
            for (int ti = 0; ti < 4; ti++) {
                int row = wr * 64 + ti * 16 + rowoffA + l7;
                uint32_t addr = sA + (row << 7) + (((2 * j + segoffA) ^ (row & 7)) << 4);
                ldsm4(a[ti][0], a[ti][1], a[ti][2], a[ti][3], addr);
            }
            #pragma unroll
            for (int tp = 0; tp < 4; tp++) {
                int row = wc * 64 + tp * 16 + rowoffB + l7;
                uint32_t addr = sB + (row << 7) + (((2 * j + segoffB) ^ (row & 7)) << 4);
                uint32_t r0, r1, r2, r3;
                ldsm4(r0, r1, r2, r3, addr);
                b[2 * tp][0] = r0; b[2 * tp][1] = r1;
                b[2 * tp + 1][0] = r2; b[2 * tp + 1][1] = r3;
            }
            #pragma unroll
            for (int ti = 0; ti < 4; ti++)
                #pragma unroll
                for (int tj = 0; tj < 8; tj++) {
                    asm volatile(
                        "mma.sync.aligned.m16n8k16.row.col.f32.f16.f16.f32 "
                        "{%0,%1,%2,%3}, {%4,%5,%6,%7}, {%8,%9}, {%0,%1,%2,%3};\n"
                        : "+f"(c[ti][tj][0]), "+f"(c[ti][tj][1]),
                          "+f"(c[ti][tj][2]), "+f"(c[ti][tj][3])
                        : "r"(a[ti][0]), "r"(a[ti][1]), "r"(a[ti][2]), "r"(a[ti][3]),
                          "r"(b[tj][0]), "r"(b[tj][1]));
                }
        }
    }

    // epilogue
    #pragma unroll
    for (int ti = 0; ti < 4; ti++) {
        int r0 = bm + wr * 64 + ti * 16 + g;
        #pragma unroll
        for (int tj = 0; tj < 8; tj++) {
            int cn = bn + wc * 64 + tj * 8 + t * 2;
            float v[4] = {c[ti][tj][0], c[ti][tj][1], c[ti][tj][2], c[ti][tj][3]};
            if (BIAS) {
                float b0 = bias[cn], b1 = bias[cn + 1];
                v[0] += b0; v[1] += b1; v[2] += b0; v[3] += b1;
            }
            if (GELU) {
                #pragma unroll
                for (int q = 0; q < 4; q++)
                    v[q] = 0.5f * v[q] * (1.0f + erff(v[q] * 0.70710678118654752f));
            }
            if (RES) {
                float2 r0v = *(const float2*)&res[(size_t)r0 * Nout + cn];
                float2 r1v = *(const float2*)&res[(size_t)(r0 + 8) * Nout + cn];
                v[0] += r0v.x; v[1] += r0v.y; v[2] += r1v.x; v[3] += r1v.y;
            }
            if (OUTH) {
                *(__half2*)&outh[(size_t)r0 * Nout + cn]       = __floats2half2_rn(v[0], v[1]);
                *(__half2*)&outh[(size_t)(r0 + 8) * Nout + cn] = __floats2half2_rn(v[2], v[3]);
            } else {
                *(float2*)&outf[(size_t)r0 * Nout + cn]       = make_float2(v[0], v[1]);
                *(float2*)&outf[(size_t)(r0 + 8) * Nout + cn] = make_float2(v[2], v[3]);
            }
        }
    }
}

// ---------------- fused attention: scores + top-16 + softmax -> fp16 ----------------
__global__ void attn_topk_kernel(const __half* __restrict__ qk, __half* __restrict__ a) {
    int bh = blockIdx.x;
    int b = bh / H_, h = bh % H_;
    extern __shared__ float sm[];
    float* Qs = sm;
    float* Ks = sm + N_ * HD_;

    int tid = threadIdx.x, lane = tid & 31, warp = tid >> 5;
    int nwarp = blockDim.x >> 5;

    const __half* base = qk + (size_t)b * N_ * (2 * C_);
    for (int e = tid; e < N_ * HD_; e += blockDim.x) {
        int n = e / HD_, d = e % HD_;
        Qs[n * HD_ + d] = __half2float(base[(size_t)n * (2 * C_) + h * HD_ + d]) * SCALE_;
        Ks[n * 65 + d]  = __half2float(base[(size_t)n * (2 * C_) + C_ + h * HD_ + d]);
    }
    __syncthreads();

    for (int i = warp; i < N_; i += nwarp) {
        int jj[7];
        float sloc[7];
        #pragma unroll
        for (int t2 = 0; t2 < 7; t2++) {
            int j = lane + 32 * t2;
            jj[t2] = (j < N_) ? j : 0;
            sloc[t2] = 0.f;
        }
        const float* qrow = Qs + i * HD_;
        #pragma unroll 8
        for (int d = 0; d < HD_; d++) {
            float qv = qrow[d];
            #pragma unroll
            for (int t2 = 0; t2 < 7; t2++) sloc[t2] += qv * Ks[jj[t2] * 65 + d];
        }
        #pragma unroll
        for (int t2 = 0; t2 < 7; t2++)
            if (lane + 32 * t2 >= N_) sloc[t2] = -INFINITY;

        float top[16];
        #pragma unroll
        for (int sel = 0; sel < TOPK_; sel++) {
            float m = sloc[0]; int tl = 0;
            #pragma unroll
            for (int t2 = 1; t2 < 7; t2++)
                if (sloc[t2] > m) { m = sloc[t2]; tl = t2; }
            int key = (lane << 3) | tl;
            #pragma unroll
            for (int o = 16; o > 0; o >>= 1) {
                float om = __shfl_xor_sync(0xffffffffu, m, o);
                int ok   = __shfl_xor_sync(0xffffffffu, key, o);
                if (om > m || (om == m && ok < key)) { m = om; key = ok; }
            }
            top[sel] = m;
            if (lane == (key >> 3)) sloc[key & 7] = -INFINITY;
        }

        float ssum = 0.f;
        #pragma unroll
        for (int t2 = 0; t2 < TOPK_; t2++) ssum += expf(top[t2] - top[0]);
        if (lane < TOPK_) {
            float val = expf(top[lane] - top[0]) / ssum;
            a[((size_t)(b * N_ + i)) * (H_ * TOPK_) + h * TOPK_ + lane] = __float2half(val);
        }
    }
}

// ---------------- launch ----------------
extern "C" void kernel_launch(void* const* d_in, const int* in_sizes, int n_in,
                              void* d_out, int out_size) {
    const float* x      = (const float*)d_in[0];
    const float* n1g    = (const float*)d_in[1];
    const float* n1b    = (const float*)d_in[2];
    const float* qk_w   = (const float*)d_in[3];
    const float* proj_w = (const float*)d_in[4];
    const float* proj_b = (const float*)d_in[5];
    const float* n2g    = (const float*)d_in[6];
    const float* n2b    = (const float*)d_in[7];
    const float* fc1_w  = (const float*)d_in[8];
    const float* fc1_b  = (const float*)d_in[9];
    const float* fc2_w  = (const float*)d_in[10];
    const float* fc2_b  = (const float*)d_in[11];
    float* out = (float*)d_out;

    __half *h_h, *qk_h, *a_h, *hid_h, *qkw_h, *pw_h, *f1w_h, *f2w_h;
    float *x1;
    cudaGetSymbolAddress((void**)&h_h,   g_h_h);
    cudaGetSymbolAddress((void**)&qk_h,  g_qk_h);
    cudaGetSymbolAddress((void**)&a_h,   g_a_h);
    cudaGetSymbolAddress((void**)&x1,    g_x1);
    cudaGetSymbolAddress((void**)&hid_h, g_hid_h);
    cudaGetSymbolAddress((void**)&qkw_h, g_qkw_h);
    cudaGetSymbolAddress((void**)&pw_h,  g_pw_h);
    cudaGetSymbolAddress((void**)&f1w_h, g_f1w_h);
    cudaGetSymbolAddress((void**)&f2w_h, g_f2w_h);

    cudaFuncSetAttribute((const void*)gemm_h<false,false,false,true>, cudaFuncAttributeMaxDynamicSharedMemorySize, SMEM_SZ);
    cudaFuncSetAttribute((const void*)gemm_h<true,false,true,false>,  cudaFuncAttributeMaxDynamicSharedMemorySize, SMEM_SZ);
    cudaFuncSetAttribute((const void*)gemm_h<true,true,false,true>,   cudaFuncAttributeMaxDynamicSharedMemorySize, SMEM_SZ);

    // weight conversions (fp32 -> fp16)
    {
        int n;
        n = 2 * C_ * C_;     cvt_kernel<<<(n / 2 + 255) / 256, 256>>>(qk_w,   qkw_h, n);
        n = C_ * H_ * TOPK_; cvt_kernel<<<(n / 2 + 255) / 256, 256>>>(proj_w, pw_h,  n);
        n = HID_ * C_;       cvt_kernel<<<(n / 2 + 255) / 256, 256>>>(fc1_w,  f1w_h, n);
        n = C_ * HID_;       cvt_kernel<<<(n / 2 + 255) / 256, 256>>>(fc2_w,  f2w_h, n);
    }

    // 1. LN1 -> fp16
    ln_kernel<<<M_, 256>>>(x, n1g, n1b, h_h);

    // 2. qk = h @ qk_w^T   [M, 1536], K=768 (fp16 out)
    gemm_h<false, false, false, true><<<dim3((2 * C_) / 256, M_ / 128), 256, SMEM_SZ>>>(
        h_h, qkw_h, nullptr, nullptr, nullptr, qk_h, 2 * C_, C_);

    // 3. attention -> a fp16 [M, 192]
    int smem = (N_ * HD_ + N_ * 65) * (int)sizeof(float);
    cudaFuncSetAttribute(attn_topk_kernel, cudaFuncAttributeMaxDynamicSharedMemorySize, smem);
    attn_topk_kernel<<<B_ * H_, 256, smem>>>(qk_h, a_h);

    // 4. x1 = x + a @ proj_w^T + proj_b   [M, 768], K=192
    gemm_h<true, false, true, false><<<dim3(C_ / 256, M_ / 128), 256, SMEM_SZ>>>(
        a_h, pw_h, proj_b, x, x1, nullptr, C_, H_ * TOPK_);

    // 5. LN2 -> fp16
    ln_kernel<<<M_, 256>>>(x1, n2g, n2b, h_h);

    // 6. hid = gelu(h @ fc1_w^T + fc1_b) -> fp16 [M, 3072], K=768
    gemm_h<true, true, false, true><<<dim3(HID_ / 256, M_ / 128), 256, SMEM_SZ>>>(
        h_h, f1w_h, fc1_b, nullptr, nullptr, hid_h, HID_, C_);

    // 7. out = x1 + hid @ fc2_w^T + fc2_b  [M, 768], K=3072
    gemm_h<true, false, true, false><<<dim3(C_ / 256, M_ / 128), 256, SMEM_SZ>>>(
        hid_h, f2w_h, fc2_b, x1, out, nullptr, C_, HID_);
}

// round 9
// speedup vs baseline: 1.0792x; 1.0792x over previous
#include <cuda_runtime.h>
#include <cuda_fp16.h>
#include <math.h>
#include <stdint.h>

#define B_   64
#define N_   196
#define C_   768
#define H_   12
#define HD_  64
#define TOPK_ 16
#define HID_ 3072
#define M_   (B_ * N_)          // 12544
#define SCALE_ 0.125f
#define EPS_ 1e-5f

// ---------------- scratch (device globals) ----------------
__device__ __half g_h_h  [(size_t)M_ * C_];
__device__ __half g_qk_h [(size_t)M_ * 2 * C_];
__device__ __half g_a_h  [(size_t)M_ * H_ * TOPK_];
__device__ float  g_x1   [(size_t)M_ * C_];
__device__ __half g_hid_h[(size_t)M_ * HID_];
// fp16 weights
__device__ __half g_qkw_h[(size_t)2 * C_ * C_];
__device__ __half g_pw_h [(size_t)C_ * H_ * TOPK_];
__device__ __half g_f1w_h[(size_t)HID_ * C_];
__device__ __half g_f2w_h[(size_t)C_ * HID_];

// ---------------- helpers ----------------
__device__ __forceinline__ void cp_async16(void* smem, const void* gmem) {
    uint32_t s = (uint32_t)__cvta_generic_to_shared(smem);
    asm volatile("cp.async.cg.shared.global [%0], [%1], 16;\n" :: "r"(s), "l"(gmem));
}
__device__ __forceinline__ void cp_commit() { asm volatile("cp.async.commit_group;\n"); }
template <int Np>
__device__ __forceinline__ void cp_wait() { asm volatile("cp.async.wait_group %0;\n" :: "n"(Np) : "memory"); }
__device__ __forceinline__ void ldsm4(uint32_t& r0, uint32_t& r1, uint32_t& r2, uint32_t& r3,
                                      uint32_t addr) {
    asm volatile("ldmatrix.sync.aligned.m8n8.x4.shared.b16 {%0,%1,%2,%3}, [%4];\n"
                 : "=r"(r0), "=r"(r1), "=r"(r2), "=r"(r3) : "r"(addr));
}

// ---------------- weight fp32 -> fp16 (float4 vectorized) ----------------
__global__ void cvt_kernel(const float* __restrict__ src, __half* __restrict__ dst, int n) {
    int i = (blockIdx.x * 256 + threadIdx.x) * 4;
    if (i < n) {
        float4 v = *(const float4*)&src[i];
        __half2 h0 = __floats2half2_rn(v.x, v.y);
        __half2 h1 = __floats2half2_rn(v.z, v.w);
        *(uint2*)&dst[i] = make_uint2(*(uint32_t*)&h0, *(uint32_t*)&h1);
    }
}

// ---------------- LayerNorm -> fp16 (float4 vectorized, 192 threads) ----------------
__global__ void ln_kernel(const float* __restrict__ x, const float* __restrict__ g,
                          const float* __restrict__ b, __half* __restrict__ out) {
    int row = blockIdx.x;
    const float4* xr = (const float4*)(x + (size_t)row * C_);
    int tid = threadIdx.x, lane = tid & 31, warp = tid >> 5;   // 192 threads, 6 warps

    float4 v = xr[tid];
    float s  = v.x + v.y + v.z + v.w;
    float s2 = v.x * v.x + v.y * v.y + v.z * v.z + v.w * v.w;
    #pragma unroll
    for (int o = 16; o > 0; o >>= 1) {
        s  += __shfl_xor_sync(0xffffffffu, s,  o);
        s2 += __shfl_xor_sync(0xffffffffu, s2, o);
    }
    __shared__ float shs[6], shs2[6], sh_mu, sh_inv;
    if (lane == 0) { shs[warp] = s; shs2[warp] = s2; }
    __syncthreads();
    if (tid == 0) {
        float ts = 0.f, ts2 = 0.f;
        #pragma unroll
        for (int w = 0; w < 6; w++) { ts += shs[w]; ts2 += shs2[w]; }
        float mu = ts / C_;
        sh_mu = mu; sh_inv = rsqrtf(ts2 / C_ - mu * mu + EPS_);
    }
    __syncthreads();
    float mu = sh_mu, inv = sh_inv;
    float4 gv = ((const float4*)g)[tid];
    float4 bv = ((const float4*)b)[tid];
    float o0 = (v.x - mu) * inv * gv.x + bv.x;
    float o1 = (v.y - mu) * inv * gv.y + bv.y;
    float o2 = (v.z - mu) * inv * gv.z + bv.z;
    float o3 = (v.w - mu) * inv * gv.w + bv.w;
    __half2 h0 = __floats2half2_rn(o0, o1);
    __half2 h1 = __floats2half2_rn(o2, o3);
    *(uint2*)&out[(size_t)row * C_ + tid * 4] = make_uint2(*(uint32_t*)&h0, *(uint32_t*)&h1);
}

// ---------------- FP16 mma.sync GEMM ----------------
// out[M,Nout] = A[M,K] @ W[Nout,K]^T (+bias)(gelu)(+res), fp32 accumulate.
// BM=BN=128, BK=64 (128B fp16 rows). 128 threads = 4 warps (2x2), warp tile 64x64.
// 3-stage cp.async, SW128 swizzle, ldmatrix.x4, m16n8k16. 2 CTAs/SM.
#define STG_B 32768               // (128+128) rows * 128 B
#define NSTG  3
#define SMEM_SZ (NSTG * STG_B)

template <bool BIAS, bool GELU, bool RES, bool OUTH>
__global__ __launch_bounds__(128, 2) void gemm_h(
        const __half* __restrict__ A, const __half* __restrict__ W,
        const float* __restrict__ bias, const float* __restrict__ res,
        float* __restrict__ outf, __half* __restrict__ outh, int Nout, int K) {
    extern __shared__ char smem[];
    uint32_t sb = (uint32_t)__cvta_generic_to_shared(smem);

    int tid = threadIdx.x;
    int lane = tid & 31, wid = tid >> 5;
    int wr = wid >> 1, wc = wid & 1;
    int g = lane >> 2, t = lane & 3;
    int grp = lane >> 3, l7 = lane & 7;
    int bm = blockIdx.y * 128, bn = blockIdx.x * 128;

    const __half* Ablk = A + (size_t)bm * K;
    const __half* Wblk = W + (size_t)bn * K;

    float c[4][8][4];
    #pragma unroll
    for (int i = 0; i < 4; i++)
        #pragma unroll
        for (int j = 0; j < 8; j++)
            #pragma unroll
            for (int r = 0; r < 4; r++) c[i][j][r] = 0.f;

    // loader: 2048 16B tasks / 128 threads = 16
    int lrow0 = tid >> 3;
    int lseg  = tid & 7;
    uint32_t lcol = (uint32_t)((lseg ^ (lrow0 & 7)) << 4);
    auto load_stage = [&](int slot, int k0) {
        char* sbase = smem + slot * STG_B;
        #pragma unroll
        for (int i = 0; i < 16; i++) {
            int row = lrow0 + (i & 7) * 16;
            int isB = i >> 3;
            const __half* src = (isB ? Wblk : Ablk) + (size_t)row * K + k0 + lseg * 8;
            char* dst = sbase + isB * 16384 + row * 128 + lcol;
            cp_async16(dst, src);
        }
        cp_commit();
    };

    int NK = K / 64;
    load_stage(0, 0);
    load_stage(1, 64);

    int rowoffA = (grp & 1) * 8, segoffA = grp >> 1;
    int rowoffB = (grp >> 1) * 8, segoffB = grp & 1;

    for (int kc = 0; kc < NK; kc++) {
        int slot = kc % NSTG;
        cp_wait<1>();
        __syncthreads();

        if (kc + 2 < NK) load_stage((kc + 2) % NSTG, (kc + 2) * 64);
        else cp_commit();

        uint32_t sA = sb + slot * STG_B;
        uint32_t sB = sA + 16384;

        #pragma unroll
        for (int j = 0; j < 4; j++) {         // 4 k16-steps in BK=64
            uint32_t a[4][4], b[8][2];
            #pragma unroll
            for (int ti = 0; ti < 4; ti++) {
                int row = wr * 64 + ti * 16 + rowoffA + l7;
                uint32_t addr = sA + (row << 7) + (((2 * j + segoffA) ^ (row & 7)) << 4);
                ldsm4(a[ti][0], a[ti][1], a[ti][2], a[ti][3], addr);
            }
            #pragma unroll
            for (int tp = 0; tp < 4; tp++) {
                int row = wc * 64 + tp * 16 + rowoffB + l7;
                uint32_t addr = sB + (row << 7) + (((2 * j + segoffB) ^ (row & 7)) << 4);
                uint32_t r0, r1, r2, r3;
                ldsm4(r0, r1, r2, r3, addr);
                b[2 * tp][0] = r0; b[2 * tp][1] = r1;
                b[2 * tp + 1][0] = r2; b[2 * tp + 1][1] = r3;
            }
            #pragma unroll
            for (int ti = 0; ti < 4; ti++)
                #pragma unroll
                for (int tj = 0; tj < 8; tj++) {
                    asm volatile(
                        "mma.sync.aligned.m16n8k16.row.col.f32.f16.f16.f32 "
                        "{%0,%1,%2,%3}, {%4,%5,%6,%7}, {%8,%9}, {%0,%1,%2,%3};\n"
                        : "+f"(c[ti][tj][0]), "+f"(c[ti][tj][1]),
                          "+f"(c[ti][tj][2]), "+f"(c[ti][tj][3])
                        : "r"(a[ti][0]), "r"(a[ti][1]), "r"(a[ti][2]), "r"(a[ti][3]),
                          "r"(b[tj][0]), "r"(b[tj][1]));
                }
        }
    }

    // epilogue
    #pragma unroll
    for (int ti = 0; ti < 4; ti++) {
        int r0 = bm + wr * 64 + ti * 16 + g;
        #pragma unroll
        for (int tj = 0; tj < 8; tj++) {
            int cn = bn + wc * 64 + tj * 8 + t * 2;
            float v[4] = {c[ti][tj][0], c[ti][tj][1], c[ti][tj][2], c[ti][tj][3]};
            if (BIAS) {
                float b0 = bias[cn], b1 = bias[cn + 1];
                v[0] += b0; v[1] += b1; v[2] += b0; v[3] += b1;
            }
            if (GELU) {
                #pragma unroll
                for (int q = 0; q < 4; q++)
                    v[q] = 0.5f * v[q] * (1.0f + erff(v[q] * 0.70710678118654752f));
            }
            if (RES) {
                float2 r0v = *(const float2*)&res[(size_t)r0 * Nout + cn];
                float2 r1v = *(const float2*)&res[(size_t)(r0 + 8) * Nout + cn];
                v[0] += r0v.x; v[1] += r0v.y; v[2] += r1v.x; v[3] += r1v.y;
            }
            if (OUTH) {
                *(__half2*)&outh[(size_t)r0 * Nout + cn]       = __floats2half2_rn(v[0], v[1]);
                *(__half2*)&outh[(size_t)(r0 + 8) * Nout + cn] = __floats2half2_rn(v[2], v[3]);
            } else {
                *(float2*)&outf[(size_t)r0 * Nout + cn]       = make_float2(v[0], v[1]);
                *(float2*)&outf[(size_t)(r0 + 8) * Nout + cn] = make_float2(v[2], v[3]);
            }
        }
    }
}

// ---------------- fused attention: scores + top-16 + softmax -> fp16 ----------------
__global__ void attn_topk_kernel(const __half* __restrict__ qk, __half* __restrict__ a) {
    int bh = blockIdx.x;
    int b = bh / H_, h = bh % H_;
    extern __shared__ float sm[];
    float* Qs = sm;
    float* Ks = sm + N_ * HD_;

    int tid = threadIdx.x, lane = tid & 31, warp = tid >> 5;
    int nwarp = blockDim.x >> 5;

    const __half* base = qk + (size_t)b * N_ * (2 * C_);
    for (int e = tid; e < N_ * HD_; e += blockDim.x) {
        int n = e / HD_, d = e % HD_;
        Qs[n * HD_ + d] = __half2float(base[(size_t)n * (2 * C_) + h * HD_ + d]) * SCALE_;
        Ks[n * 65 + d]  = __half2float(base[(size_t)n * (2 * C_) + C_ + h * HD_ + d]);
    }
    __syncthreads();

    for (int i = warp; i < N_; i += nwarp) {
        int jj[7];
        float sloc[7];
        #pragma unroll
        for (int t2 = 0; t2 < 7; t2++) {
            int j = lane + 32 * t2;
            jj[t2] = (j < N_) ? j : 0;
            sloc[t2] = 0.f;
        }
        const float* qrow = Qs + i * HD_;
        #pragma unroll 8
        for (int d = 0; d < HD_; d++) {
            float qv = qrow[d];
            #pragma unroll
            for (int t2 = 0; t2 < 7; t2++) sloc[t2] += qv * Ks[jj[t2] * 65 + d];
        }
        #pragma unroll
        for (int t2 = 0; t2 < 7; t2++)
            if (lane + 32 * t2 >= N_) sloc[t2] = -INFINITY;

        float top[16];
        #pragma unroll
        for (int sel = 0; sel < TOPK_; sel++) {
            float m = sloc[0]; int tl = 0;
            #pragma unroll
            for (int t2 = 1; t2 < 7; t2++)
                if (sloc[t2] > m) { m = sloc[t2]; tl = t2; }
            int key = (lane << 3) | tl;
            #pragma unroll
            for (int o = 16; o > 0; o >>= 1) {
                float om = __shfl_xor_sync(0xffffffffu, m, o);
                int ok   = __shfl_xor_sync(0xffffffffu, key, o);
                if (om > m || (om == m && ok < key)) { m = om; key = ok; }
            }
            top[sel] = m;
            if (lane == (key >> 3)) sloc[key & 7] = -INFINITY;
        }

        float ssum = 0.f;
        #pragma unroll
        for (int t2 = 0; t2 < TOPK_; t2++) ssum += expf(top[t2] - top[0]);
        if (lane < TOPK_) {
            float val = expf(top[lane] - top[0]) / ssum;
            a[((size_t)(b * N_ + i)) * (H_ * TOPK_) + h * TOPK_ + lane] = __float2half(val);
        }
    }
}

// ---------------- launch ----------------
extern "C" void kernel_launch(void* const* d_in, const int* in_sizes, int n_in,
                              void* d_out, int out_size) {
    const float* x      = (const float*)d_in[0];
    const float* n1g    = (const float*)d_in[1];
    const float* n1b    = (const float*)d_in[2];
    const float* qk_w   = (const float*)d_in[3];
    const float* proj_w = (const float*)d_in[4];
    const float* proj_b = (const float*)d_in[5];
    const float* n2g    = (const float*)d_in[6];
    const float* n2b    = (const float*)d_in[7];
    const float* fc1_w  = (const float*)d_in[8];
    const float* fc1_b  = (const float*)d_in[9];
    const float* fc2_w  = (const float*)d_in[10];
    const float* fc2_b  = (const float*)d_in[11];
    float* out = (float*)d_out;

    __half *h_h, *qk_h, *a_h, *hid_h, *qkw_h, *pw_h, *f1w_h, *f2w_h;
    float *x1;
    cudaGetSymbolAddress((void**)&h_h,   g_h_h);
    cudaGetSymbolAddress((void**)&qk_h,  g_qk_h);
    cudaGetSymbolAddress((void**)&a_h,   g_a_h);
    cudaGetSymbolAddress((void**)&x1,    g_x1);
    cudaGetSymbolAddress((void**)&hid_h, g_hid_h);
    cudaGetSymbolAddress((void**)&qkw_h, g_qkw_h);
    cudaGetSymbolAddress((void**)&pw_h,  g_pw_h);
    cudaGetSymbolAddress((void**)&f1w_h, g_f1w_h);
    cudaGetSymbolAddress((void**)&f2w_h, g_f2w_h);

    cudaFuncSetAttribute((const void*)gemm_h<false,false,false,true>, cudaFuncAttributeMaxDynamicSharedMemorySize, SMEM_SZ);
    cudaFuncSetAttribute((const void*)gemm_h<true,false,true,false>,  cudaFuncAttributeMaxDynamicSharedMemorySize, SMEM_SZ);
    cudaFuncSetAttribute((const void*)gemm_h<true,true,false,true>,   cudaFuncAttributeMaxDynamicSharedMemorySize, SMEM_SZ);

    // weight conversions (fp32 -> fp16)
    {
        int n;
        n = 2 * C_ * C_;     cvt_kernel<<<(n / 4 + 255) / 256, 256>>>(qk_w,   qkw_h, n);
        n = C_ * H_ * TOPK_; cvt_kernel<<<(n / 4 + 255) / 256, 256>>>(proj_w, pw_h,  n);
        n = HID_ * C_;       cvt_kernel<<<(n / 4 + 255) / 256, 256>>>(fc1_w,  f1w_h, n);
        n = C_ * HID_;       cvt_kernel<<<(n / 4 + 255) / 256, 256>>>(fc2_w,  f2w_h, n);
    }

    // 1. LN1 -> fp16
    ln_kernel<<<M_, 192>>>(x, n1g, n1b, h_h);

    // 2. qk = h @ qk_w^T   [M, 1536], K=768 (fp16 out)
    gemm_h<false, false, false, true><<<dim3((2 * C_) / 128, M_ / 128), 128, SMEM_SZ>>>(
        h_h, qkw_h, nullptr, nullptr, nullptr, qk_h, 2 * C_, C_);

    // 3. attention -> a fp16 [M, 192]
    int smem = (N_ * HD_ + N_ * 65) * (int)sizeof(float);
    cudaFuncSetAttribute(attn_topk_kernel, cudaFuncAttributeMaxDynamicSharedMemorySize, smem);
    attn_topk_kernel<<<B_ * H_, 256, smem>>>(qk_h, a_h);

    // 4. x1 = x + a @ proj_w^T + proj_b   [M, 768], K=192
    gemm_h<true, false, true, false><<<dim3(C_ / 128, M_ / 128), 128, SMEM_SZ>>>(
        a_h, pw_h, proj_b, x, x1, nullptr, C_, H_ * TOPK_);

    // 5. LN2 -> fp16
    ln_kernel<<<M_, 192>>>(x1, n2g, n2b, h_h);

    // 6. hid = gelu(h @ fc1_w^T + fc1_b) -> fp16 [M, 3072], K=768
    gemm_h<true, true, false, true><<<dim3(HID_ / 128, M_ / 128), 128, SMEM_SZ>>>(
        h_h, f1w_h, fc1_b, nullptr, nullptr, hid_h, HID_, C_);

    // 7. out = x1 + hid @ fc2_w^T + fc2_b  [M, 768], K=3072
    gemm_h<true, false, true, false><<<dim3(C_ / 128, M_ / 128), 128, SMEM_SZ>>>(
        hid_h, f2w_h, fc2_b, x1, out, nullptr, C_, HID_);
}

// round 10
// speedup vs baseline: 1.1791x; 1.0926x over previous
#include <cuda_runtime.h>
#include <cuda_fp16.h>
#include <math.h>
#include <stdint.h>

#define B_   64
#define N_   196
#define C_   768
#define H_   12
#define HD_  64
#define TOPK_ 16
#define HID_ 3072
#define M_   (B_ * N_)          // 12544
#define SCALE_ 0.125f
#define EPS_ 1e-5f

// ---------------- scratch (device globals) ----------------
__device__ __half g_h_h  [(size_t)M_ * C_];
__device__ __half g_qk_h [(size_t)M_ * 2 * C_];
__device__ __half g_a_h  [(size_t)M_ * H_ * TOPK_];
__device__ float  g_x1   [(size_t)M_ * C_];
__device__ __half g_hid_h[(size_t)M_ * HID_];
// fp16 weights
__device__ __half g_qkw_h[(size_t)2 * C_ * C_];
__device__ __half g_pw_h [(size_t)C_ * H_ * TOPK_];
__device__ __half g_f1w_h[(size_t)HID_ * C_];
__device__ __half g_f2w_h[(size_t)C_ * HID_];

// ---------------- helpers ----------------
__device__ __forceinline__ void cp_async16(void* smem, const void* gmem) {
    uint32_t s = (uint32_t)__cvta_generic_to_shared(smem);
    asm volatile("cp.async.cg.shared.global [%0], [%1], 16;\n" :: "r"(s), "l"(gmem));
}
__device__ __forceinline__ void cp_commit() { asm volatile("cp.async.commit_group;\n"); }
template <int Np>
__device__ __forceinline__ void cp_wait() { asm volatile("cp.async.wait_group %0;\n" :: "n"(Np) : "memory"); }
__device__ __forceinline__ void ldsm4(uint32_t& r0, uint32_t& r1, uint32_t& r2, uint32_t& r3,
                                      uint32_t addr) {
    asm volatile("ldmatrix.sync.aligned.m8n8.x4.shared.b16 {%0,%1,%2,%3}, [%4];\n"
                 : "=r"(r0), "=r"(r1), "=r"(r2), "=r"(r3) : "r"(addr));
}

// ---------------- weight fp32 -> fp16 (float4 vectorized) ----------------
__global__ void cvt_kernel(const float* __restrict__ src, __half* __restrict__ dst, int n) {
    int i = (blockIdx.x * 256 + threadIdx.x) * 4;
    if (i < n) {
        float4 v = *(const float4*)&src[i];
        __half2 h0 = __floats2half2_rn(v.x, v.y);
        __half2 h1 = __floats2half2_rn(v.z, v.w);
        *(uint2*)&dst[i] = make_uint2(*(uint32_t*)&h0, *(uint32_t*)&h1);
    }
}

// ---------------- LayerNorm -> fp16 (float4 vectorized, 192 threads) ----------------
__global__ void ln_kernel(const float* __restrict__ x, const float* __restrict__ g,
                          const float* __restrict__ b, __half* __restrict__ out) {
    int row = blockIdx.x;
    const float4* xr = (const float4*)(x + (size_t)row * C_);
    int tid = threadIdx.x, lane = tid & 31, warp = tid >> 5;   // 192 threads, 6 warps

    float4 v = xr[tid];
    float s  = v.x + v.y + v.z + v.w;
    float s2 = v.x * v.x + v.y * v.y + v.z * v.z + v.w * v.w;
    #pragma unroll
    for (int o = 16; o > 0; o >>= 1) {
        s  += __shfl_xor_sync(0xffffffffu, s,  o);
        s2 += __shfl_xor_sync(0xffffffffu, s2, o);
    }
    __shared__ float shs[6], shs2[6], sh_mu, sh_inv;
    if (lane == 0) { shs[warp] = s; shs2[warp] = s2; }
    __syncthreads();
    if (tid == 0) {
        float ts = 0.f, ts2 = 0.f;
        #pragma unroll
        for (int w = 0; w < 6; w++) { ts += shs[w]; ts2 += shs2[w]; }
        float mu = ts / C_;
        sh_mu = mu; sh_inv = rsqrtf(ts2 / C_ - mu * mu + EPS_);
    }
    __syncthreads();
    float mu = sh_mu, inv = sh_inv;
    float4 gv = ((const float4*)g)[tid];
    float4 bv = ((const float4*)b)[tid];
    float o0 = (v.x - mu) * inv * gv.x + bv.x;
    float o1 = (v.y - mu) * inv * gv.y + bv.y;
    float o2 = (v.z - mu) * inv * gv.z + bv.z;
    float o3 = (v.w - mu) * inv * gv.w + bv.w;
    __half2 h0 = __floats2half2_rn(o0, o1);
    __half2 h1 = __floats2half2_rn(o2, o3);
    *(uint2*)&out[(size_t)row * C_ + tid * 4] = make_uint2(*(uint32_t*)&h0, *(uint32_t*)&h1);
}

// ---------------- FP16 mma.sync GEMM ----------------
// out[M,Nout] = A[M,K] @ W[Nout,K]^T (+bias)(gelu)(+res), fp32 accumulate.
// BM=BN=128, BK=64 (128B fp16 rows). 128 threads = 4 warps (2x2), warp tile 64x64.
// 3-stage cp.async, SW128 swizzle, ldmatrix.x4, m16n8k16. 2 CTAs/SM.
#define STG_B 32768               // (128+128) rows * 128 B
#define NSTG  3
#define SMEM_SZ (NSTG * STG_B)

template <bool BIAS, bool GELU, bool RES, bool OUTH>
__global__ __launch_bounds__(128, 2) void gemm_h(
        const __half* __restrict__ A, const __half* __restrict__ W,
        const float* __restrict__ bias, const float* __restrict__ res,
        float* __restrict__ outf, __half* __restrict__ outh, int Nout, int K) {
    extern __shared__ char smem[];
    uint32_t sb = (uint32_t)__cvta_generic_to_shared(smem);

    int tid = threadIdx.x;
    int lane = tid & 31, wid = tid >> 5;
    int wr = wid >> 1, wc = wid & 1;
    int g = lane >> 2, t = lane & 3;
    int grp = lane >> 3, l7 = lane & 7;
    int bm = blockIdx.y * 128, bn = blockIdx.x * 128;

    const __half* Ablk = A + (size_t)bm * K;
    const __half* Wblk = W + (size_t)bn * K;

    float c[4][8][4];
    #pragma unroll
    for (int i = 0; i < 4; i++)
        #pragma unroll
        for (int j = 0; j < 8; j++)
            #pragma unroll
            for (int r = 0; r < 4; r++) c[i][j][r] = 0.f;

    // loader: 2048 16B tasks / 128 threads = 16
    int lrow0 = tid >> 3;
    int lseg  = tid & 7;
    uint32_t lcol = (uint32_t)((lseg ^ (lrow0 & 7)) << 4);
    auto load_stage = [&](int slot, int k0) {
        char* sbase = smem + slot * STG_B;
        #pragma unroll
        for (int i = 0; i < 16; i++) {
            int row = lrow0 + (i & 7) * 16;
            int isB = i >> 3;
            const __half* src = (isB ? Wblk : Ablk) + (size_t)row * K + k0 + lseg * 8;
            char* dst = sbase + isB * 16384 + row * 128 + lcol;
            cp_async16(dst, src);
        }
        cp_commit();
    };

    int NK = K / 64;
    load_stage(0, 0);
    load_stage(1, 64);

    int rowoffA = (grp & 1) * 8, segoffA = grp >> 1;
    int rowoffB = (grp >> 1) * 8, segoffB = grp & 1;

    for (int kc = 0; kc < NK; kc++) {
        int slot = kc % NSTG;
        cp_wait<1>();
        __syncthreads();

        if (kc + 2 < NK) load_stage((kc + 2) % NSTG, (kc + 2) * 64);
        else cp_commit();

        uint32_t sA = sb + slot * STG_B;
        uint32_t sB = sA + 16384;

        #pragma unroll
        for (int j = 0; j < 4; j++) {         // 4 k16-steps in BK=64
            uint32_t a[4][4], b[8][2];
            #pragma unroll
            for (int ti = 0; ti < 4; ti++) {
                int row = wr * 64 + ti * 16 + rowoffA + l7;
                uint32_t addr = sA + (row << 7) + (((2 * j + segoffA) ^ (row & 7)) << 4);
                ldsm4(a[ti][0], a[ti][1], a[ti][2], a[ti][3], addr);
            }
            #pragma unroll
            for (int tp = 0; tp < 4; tp++) {
                int row = wc * 64 + tp * 16 + rowoffB + l7;
                uint32_t addr = sB + (row << 7) + (((2 * j + segoffB) ^ (row & 7)) << 4);
                uint32_t r0, r1, r2, r3;
                ldsm4(r0, r1, r2, r3, addr);
                b[2 * tp][0] = r0; b[2 * tp][1] = r1;
                b[2 * tp + 1][0] = r2; b[2 * tp + 1][1] = r3;
            }
            #pragma unroll
            for (int ti = 0; ti < 4; ti++)
                #pragma unroll
                for (int tj = 0; tj < 8; tj++) {
                    asm volatile(
                        "mma.sync.aligned.m16n8k16.row.col.f32.f16.f16.f32 "
                        "{%0,%1,%2,%3}, {%4,%5,%6,%7}, {%8,%9}, {%0,%1,%2,%3};\n"
                        : "+f"(c[ti][tj][0]), "+f"(c[ti][tj][1]),
                          "+f"(c[ti][tj][2]), "+f"(c[ti][tj][3])
                        : "r"(a[ti][0]), "r"(a[ti][1]), "r"(a[ti][2]), "r"(a[ti][3]),
                          "r"(b[tj][0]), "r"(b[tj][1]));
                }
        }
    }

    // epilogue
    #pragma unroll
    for (int ti = 0; ti < 4; ti++) {
        int r0 = bm + wr * 64 + ti * 16 + g;
        #pragma unroll
        for (int tj = 0; tj < 8; tj++) {
            int cn = bn + wc * 64 + tj * 8 + t * 2;
            float v[4] = {c[ti][tj][0], c[ti][tj][1], c[ti][tj][2], c[ti][tj][3]};
            if (BIAS) {
                float b0 = bias[cn], b1 = bias[cn + 1];
                v[0] += b0; v[1] += b1; v[2] += b0; v[3] += b1;
            }
            if (GELU) {
                #pragma unroll
                for (int q = 0; q < 4; q++)
                    v[q] = 0.5f * v[q] * (1.0f + erff(v[q] * 0.70710678118654752f));
            }
            if (RES) {
                float2 r0v = *(const float2*)&res[(size_t)r0 * Nout + cn];
                float2 r1v = *(const float2*)&res[(size_t)(r0 + 8) * Nout + cn];
                v[0] += r0v.x; v[1] += r0v.y; v[2] += r1v.x; v[3] += r1v.y;
            }
            if (OUTH) {
                *(__half2*)&outh[(size_t)r0 * Nout + cn]       = __floats2half2_rn(v[0], v[1]);
                *(__half2*)&outh[(size_t)(r0 + 8) * Nout + cn] = __floats2half2_rn(v[2], v[3]);
            } else {
                *(float2*)&outf[(size_t)r0 * Nout + cn]       = make_float2(v[0], v[1]);
                *(float2*)&outf[(size_t)(r0 + 8) * Nout + cn] = make_float2(v[2], v[3]);
            }
        }
    }
}

// ---------------- fused attention: scores + top-16 + softmax -> fp16 ----------------
// Q staged in smem as fp32 (pre-scaled); K staged as packed half2 (2 MACs per 4B LDS).
#define KS_STRIDE 33   // half2 stride per row: 33*4=132B -> conflict-free lane mapping
__global__ void attn_topk_kernel(const __half* __restrict__ qk, __half* __restrict__ a) {
    int bh = blockIdx.x;
    int b = bh / H_, h = bh % H_;
    extern __shared__ float sm[];
    float*    Qs  = sm;                         // [196][64] fp32, pre-scaled
    uint32_t* Ks2 = (uint32_t*)(sm + N_ * HD_); // [196][33] half2 (32 data + 1 pad)

    int tid = threadIdx.x, lane = tid & 31, warp = tid >> 5;
    int nwarp = blockDim.x >> 5;

    const __half* base = qk + (size_t)b * N_ * (2 * C_);
    // stage: e indexes half2 pairs (196*32 per matrix)
    for (int e = tid; e < N_ * 32; e += blockDim.x) {
        int n = e >> 5, dp = e & 31;
        __half2 qh = *(const __half2*)&base[(size_t)n * (2 * C_) + h * HD_ + dp * 2];
        float2 qf = __half22float2(qh);
        Qs[n * HD_ + dp * 2]     = qf.x * SCALE_;
        Qs[n * HD_ + dp * 2 + 1] = qf.y * SCALE_;
        Ks2[n * KS_STRIDE + dp] = *(const uint32_t*)&base[(size_t)n * (2 * C_) + C_ + h * HD_ + dp * 2];
    }
    __syncthreads();

    for (int i = warp; i < N_; i += nwarp) {
        int jj[7];
        float sloc[7];
        #pragma unroll
        for (int t2 = 0; t2 < 7; t2++) {
            int j = lane + 32 * t2;
            jj[t2] = (j < N_) ? j * KS_STRIDE : 0;
            sloc[t2] = 0.f;
        }
        const float2* qrow2 = (const float2*)(Qs + i * HD_);
        #pragma unroll 4
        for (int dp = 0; dp < 32; dp++) {
            float2 qf = qrow2[dp];          // broadcast LDS.64
            #pragma unroll
            for (int t2 = 0; t2 < 7; t2++) {
                uint32_t kp = Ks2[jj[t2] + dp];
                float2 kf = __half22float2(*(__half2*)&kp);
                sloc[t2] += qf.x * kf.x + qf.y * kf.y;
            }
        }
        #pragma unroll
        for (int t2 = 0; t2 < 7; t2++)
            if (lane + 32 * t2 >= N_) sloc[t2] = -INFINITY;

        float top[16];
        #pragma unroll
        for (int sel = 0; sel < TOPK_; sel++) {
            float m = sloc[0]; int tl = 0;
            #pragma unroll
            for (int t2 = 1; t2 < 7; t2++)
                if (sloc[t2] > m) { m = sloc[t2]; tl = t2; }
            int key = (lane << 3) | tl;
            #pragma unroll
            for (int o = 16; o > 0; o >>= 1) {
                float om = __shfl_xor_sync(0xffffffffu, m, o);
                int ok   = __shfl_xor_sync(0xffffffffu, key, o);
                if (om > m || (om == m && ok < key)) { m = om; key = ok; }
            }
            top[sel] = m;
            if (lane == (key >> 3)) sloc[key & 7] = -INFINITY;
        }

        float ssum = 0.f;
        #pragma unroll
        for (int t2 = 0; t2 < TOPK_; t2++) ssum += expf(top[t2] - top[0]);
        if (lane < TOPK_) {
            float val = expf(top[lane] - top[0]) / ssum;
            a[((size_t)(b * N_ + i)) * (H_ * TOPK_) + h * TOPK_ + lane] = __float2half(val);
        }
    }
}

// ---------------- launch ----------------
extern "C" void kernel_launch(void* const* d_in, const int* in_sizes, int n_in,
                              void* d_out, int out_size) {
    const float* x      = (const float*)d_in[0];
    const float* n1g    = (const float*)d_in[1];
    const float* n1b    = (const float*)d_in[2];
    const float* qk_w   = (const float*)d_in[3];
    const float* proj_w = (const float*)d_in[4];
    const float* proj_b = (const float*)d_in[5];
    const float* n2g    = (const float*)d_in[6];
    const float* n2b    = (const float*)d_in[7];
    const float* fc1_w  = (const float*)d_in[8];
    const float* fc1_b  = (const float*)d_in[9];
    const float* fc2_w  = (const float*)d_in[10];
    const float* fc2_b  = (const float*)d_in[11];
    float* out = (float*)d_out;

    __half *h_h, *qk_h, *a_h, *hid_h, *qkw_h, *pw_h, *f1w_h, *f2w_h;
    float *x1;
    cudaGetSymbolAddress((void**)&h_h,   g_h_h);
    cudaGetSymbolAddress((void**)&qk_h,  g_qk_h);
    cudaGetSymbolAddress((void**)&a_h,   g_a_h);
    cudaGetSymbolAddress((void**)&x1,    g_x1);
    cudaGetSymbolAddress((void**)&hid_h, g_hid_h);
    cudaGetSymbolAddress((void**)&qkw_h, g_qkw_h);
    cudaGetSymbolAddress((void**)&pw_h,  g_pw_h);
    cudaGetSymbolAddress((void**)&f1w_h, g_f1w_h);
    cudaGetSymbolAddress((void**)&f2w_h, g_f2w_h);

    cudaFuncSetAttribute((const void*)gemm_h<false,false,false,true>, cudaFuncAttributeMaxDynamicSharedMemorySize, SMEM_SZ);
    cudaFuncSetAttribute((const void*)gemm_h<true,false,true,false>,  cudaFuncAttributeMaxDynamicSharedMemorySize, SMEM_SZ);
    cudaFuncSetAttribute((const void*)gemm_h<true,true,false,true>,   cudaFuncAttributeMaxDynamicSharedMemorySize, SMEM_SZ);

    // weight conversions (fp32 -> fp16)
    {
        int n;
        n = 2 * C_ * C_;     cvt_kernel<<<(n / 4 + 255) / 256, 256>>>(qk_w,   qkw_h, n);
        n = C_ * H_ * TOPK_; cvt_kernel<<<(n / 4 + 255) / 256, 256>>>(proj_w, pw_h,  n);
        n = HID_ * C_;       cvt_kernel<<<(n / 4 + 255) / 256, 256>>>(fc1_w,  f1w_h, n);
        n = C_ * HID_;       cvt_kernel<<<(n / 4 + 255) / 256, 256>>>(fc2_w,  f2w_h, n);
    }

    // 1. LN1 -> fp16
    ln_kernel<<<M_, 192>>>(x, n1g, n1b, h_h);

    // 2. qk = h @ qk_w^T   [M, 1536], K=768 (fp16 out)
    gemm_h<false, false, false, true><<<dim3((2 * C_) / 128, M_ / 128), 128, SMEM_SZ>>>(
        h_h, qkw_h, nullptr, nullptr, nullptr, qk_h, 2 * C_, C_);

    // 3. attention -> a fp16 [M, 192]
    int smem = (N_ * HD_) * (int)sizeof(float) + N_ * KS_STRIDE * 4;  // ~76 KB
    cudaFuncSetAttribute(attn_topk_kernel, cudaFuncAttributeMaxDynamicSharedMemorySize, smem);
    attn_topk_kernel<<<B_ * H_, 256, smem>>>(qk_h, a_h);

    // 4. x1 = x + a @ proj_w^T + proj_b   [M, 768], K=192
    gemm_h<true, false, true, false><<<dim3(C_ / 128, M_ / 128), 128, SMEM_SZ>>>(
        a_h, pw_h, proj_b, x, x1, nullptr, C_, H_ * TOPK_);

    // 5. LN2 -> fp16
    ln_kernel<<<M_, 192>>>(x1, n2g, n2b, h_h);

    // 6. hid = gelu(h @ fc1_w^T + fc1_b) -> fp16 [M, 3072], K=768
    gemm_h<true, true, false, true><<<dim3(HID_ / 128, M_ / 128), 128, SMEM_SZ>>>(
        h_h, f1w_h, fc1_b, nullptr, nullptr, hid_h, HID_, C_);

    // 7. out = x1 + hid @ fc2_w^T + fc2_b  [M, 768], K=3072
    gemm_h<true, false, true, false><<<dim3(C_ / 128, M_ / 128), 128, SMEM_SZ>>>(
        hid_h, f2w_h, fc2_b, x1, out, nullptr, C_, HID_);
}

// round 11
// speedup vs baseline: 1.1871x; 1.0068x over previous
#include <cuda_runtime.h>
#include <cuda_fp16.h>
#include <math.h>
#include <stdint.h>

#define B_   64
#define N_   196
#define C_   768
#define H_   12
#define HD_  64
#define TOPK_ 16
#define HID_ 3072
#define M_   (B_ * N_)          // 12544
#define SCALE_ 0.125f
#define EPS_ 1e-5f

// ---------------- scratch (device globals) ----------------
__device__ __half g_h_h  [(size_t)M_ * C_];
__device__ __half g_qk_h [(size_t)M_ * 2 * C_];
__device__ __half g_a_h  [(size_t)M_ * H_ * TOPK_];
__device__ float  g_x1   [(size_t)M_ * C_];
__device__ __half g_hid_h[(size_t)M_ * HID_];
// fp16 weights
__device__ __half g_qkw_h[(size_t)2 * C_ * C_];
__device__ __half g_pw_h [(size_t)C_ * H_ * TOPK_];
__device__ __half g_f1w_h[(size_t)HID_ * C_];
__device__ __half g_f2w_h[(size_t)C_ * HID_];

// ---------------- helpers ----------------
__device__ __forceinline__ void cp_async16(void* smem, const void* gmem) {
    uint32_t s = (uint32_t)__cvta_generic_to_shared(smem);
    asm volatile("cp.async.cg.shared.global [%0], [%1], 16;\n" :: "r"(s), "l"(gmem));
}
__device__ __forceinline__ void cp_commit() { asm volatile("cp.async.commit_group;\n"); }
template <int Np>
__device__ __forceinline__ void cp_wait() { asm volatile("cp.async.wait_group %0;\n" :: "n"(Np) : "memory"); }
__device__ __forceinline__ void ldsm4(uint32_t& r0, uint32_t& r1, uint32_t& r2, uint32_t& r3,
                                      uint32_t addr) {
    asm volatile("ldmatrix.sync.aligned.m8n8.x4.shared.b16 {%0,%1,%2,%3}, [%4];\n"
                 : "=r"(r0), "=r"(r1), "=r"(r2), "=r"(r3) : "r"(addr));
}

// ---------------- merged weight fp32 -> fp16 (float4 vectorized) ----------------
__global__ void cvt4_kernel(const float* __restrict__ s0, __half* __restrict__ d0, int n0,
                            const float* __restrict__ s1, __half* __restrict__ d1, int n1,
                            const float* __restrict__ s2, __half* __restrict__ d2, int n2,
                            const float* __restrict__ s3, __half* __restrict__ d3, int n3) {
    int i = (blockIdx.x * 256 + threadIdx.x) * 4;
    const float* s; __half* d; int off;
    if (i < n0)                { s = s0; d = d0; off = 0; }
    else if (i < n0 + n1)      { s = s1; d = d1; off = n0; }
    else if (i < n0 + n1 + n2) { s = s2; d = d2; off = n0 + n1; }
    else if (i < n0 + n1 + n2 + n3) { s = s3; d = d3; off = n0 + n1 + n2; }
    else return;
    int j = i - off;
    float4 v = *(const float4*)&s[j];
    __half2 h0 = __floats2half2_rn(v.x, v.y);
    __half2 h1 = __floats2half2_rn(v.z, v.w);
    *(uint2*)&d[j] = make_uint2(*(uint32_t*)&h0, *(uint32_t*)&h1);
}

// ---------------- LayerNorm -> fp16 (float4 vectorized, 192 threads) ----------------
__global__ void ln_kernel(const float* __restrict__ x, const float* __restrict__ g,
                          const float* __restrict__ b, __half* __restrict__ out) {
    int row = blockIdx.x;
    const float4* xr = (const float4*)(x + (size_t)row * C_);
    int tid = threadIdx.x, lane = tid & 31, warp = tid >> 5;   // 192 threads, 6 warps

    float4 v = xr[tid];
    float s  = v.x + v.y + v.z + v.w;
    float s2 = v.x * v.x + v.y * v.y + v.z * v.z + v.w * v.w;
    #pragma unroll
    for (int o = 16; o > 0; o >>= 1) {
        s  += __shfl_xor_sync(0xffffffffu, s,  o);
        s2 += __shfl_xor_sync(0xffffffffu, s2, o);
    }
    __shared__ float shs[6], shs2[6], sh_mu, sh_inv;
    if (lane == 0) { shs[warp] = s; shs2[warp] = s2; }
    __syncthreads();
    if (tid == 0) {
        float ts = 0.f, ts2 = 0.f;
        #pragma unroll
        for (int w = 0; w < 6; w++) { ts += shs[w]; ts2 += shs2[w]; }
        float mu = ts / C_;
        sh_mu = mu; sh_inv = rsqrtf(ts2 / C_ - mu * mu + EPS_);
    }
    __syncthreads();
    float mu = sh_mu, inv = sh_inv;
    float4 gv = ((const float4*)g)[tid];
    float4 bv = ((const float4*)b)[tid];
    float o0 = (v.x - mu) * inv * gv.x + bv.x;
    float o1 = (v.y - mu) * inv * gv.y + bv.y;
    float o2 = (v.z - mu) * inv * gv.z + bv.z;
    float o3 = (v.w - mu) * inv * gv.w + bv.w;
    __half2 h0 = __floats2half2_rn(o0, o1);
    __half2 h1 = __floats2half2_rn(o2, o3);
    *(uint2*)&out[(size_t)row * C_ + tid * 4] = make_uint2(*(uint32_t*)&h0, *(uint32_t*)&h1);
}

// ---------------- FP16 mma.sync GEMM (frag double-buffered) ----------------
// out[M,Nout] = A[M,K] @ W[Nout,K]^T (+bias)(gelu)(+res), fp32 accumulate.
// BM=BN=128, BK=64. 128 threads = 4 warps (2x2), warp tile 64x64.
// 3-stage cp.async, SW128 swizzle, ldmatrix.x4, m16n8k16, 2 CTAs/SM.
// Fragments double-buffered across k16 steps: LDSM(j+1) overlaps MMA(j).
#define STG_B 32768               // (128+128) rows * 128 B
#define NSTG  3
#define SMEM_SZ (NSTG * STG_B)

template <bool BIAS, bool GELU, bool RES, bool OUTH>
__global__ __launch_bounds__(128, 2) void gemm_h(
        const __half* __restrict__ A, const __half* __restrict__ W,
        const float* __restrict__ bias, const float* __restrict__ res,
        float* __restrict__ outf, __half* __restrict__ outh, int Nout, int K) {
    extern __shared__ char smem[];
    uint32_t sb = (uint32_t)__cvta_generic_to_shared(smem);

    int tid = threadIdx.x;
    int lane = tid & 31, wid = tid >> 5;
    int wr = wid >> 1, wc = wid & 1;
    int g = lane >> 2, t = lane & 3;
    int grp = lane >> 3, l7 = lane & 7;
    int bm = blockIdx.y * 128, bn = blockIdx.x * 128;

    const __half* Ablk = A + (size_t)bm * K;
    const __half* Wblk = W + (size_t)bn * K;

    float c[4][8][4];
    #pragma unroll
    for (int i = 0; i < 4; i++)
        #pragma unroll
        for (int j = 0; j < 8; j++)
            #pragma unroll
            for (int r = 0; r < 4; r++) c[i][j][r] = 0.f;

    // loader: 2048 16B tasks / 128 threads = 16
    int lrow0 = tid >> 3;
    int lseg  = tid & 7;
    uint32_t lcol = (uint32_t)((lseg ^ (lrow0 & 7)) << 4);
    auto load_stage = [&](int slot, int k0) {
        char* sbase = smem + slot * STG_B;
        #pragma unroll
        for (int i = 0; i < 16; i++) {
            int row = lrow0 + (i & 7) * 16;
            int isB = i >> 3;
            const __half* src = (isB ? Wblk : Ablk) + (size_t)row * K + k0 + lseg * 8;
            char* dst = sbase + isB * 16384 + row * 128 + lcol;
            cp_async16(dst, src);
        }
        cp_commit();
    };

    int NK = K / 64;
    load_stage(0, 0);
    load_stage(1, 64);

    int rowoffA = (grp & 1) * 8, segoffA = grp >> 1;
    int rowoffB = (grp >> 1) * 8, segoffB = grp & 1;

    // fragment double buffers
    uint32_t afr[2][4][4], bfr[2][8][2];

    auto load_frags = [&](int j, int buf, uint32_t sA, uint32_t sB) {
        #pragma unroll
        for (int ti = 0; ti < 4; ti++) {
            int row = wr * 64 + ti * 16 + rowoffA + l7;
            uint32_t addr = sA + (row << 7) + (((2 * j + segoffA) ^ (row & 7)) << 4);
            ldsm4(afr[buf][ti][0], afr[buf][ti][1], afr[buf][ti][2], afr[buf][ti][3], addr);
        }
        #pragma unroll
        for (int tp = 0; tp < 4; tp++) {
            int row = wc * 64 + tp * 16 + rowoffB + l7;
            uint32_t addr = sB + (row << 7) + (((2 * j + segoffB) ^ (row & 7)) << 4);
            uint32_t r0, r1, r2, r3;
            ldsm4(r0, r1, r2, r3, addr);
            bfr[buf][2 * tp][0] = r0;     bfr[buf][2 * tp][1] = r1;
            bfr[buf][2 * tp + 1][0] = r2; bfr[buf][2 * tp + 1][1] = r3;
        }
    };

    for (int kc = 0; kc < NK; kc++) {
        int slot = kc % NSTG;
        cp_wait<1>();
        __syncthreads();

        if (kc + 2 < NK) load_stage((kc + 2) % NSTG, (kc + 2) * 64);
        else cp_commit();

        uint32_t sA = sb + slot * STG_B;
        uint32_t sB = sA + 16384;

        load_frags(0, 0, sA, sB);
        #pragma unroll
        for (int j = 0; j < 4; j++) {
            int cur = j & 1;
            if (j < 3) load_frags(j + 1, cur ^ 1, sA, sB);
            #pragma unroll
            for (int ti = 0; ti < 4; ti++)
                #pragma unroll
                for (int tj = 0; tj < 8; tj++) {
                    asm volatile(
                        "mma.sync.aligned.m16n8k16.row.col.f32.f16.f16.f32 "
                        "{%0,%1,%2,%3}, {%4,%5,%6,%7}, {%8,%9}, {%0,%1,%2,%3};\n"
                        : "+f"(c[ti][tj][0]), "+f"(c[ti][tj][1]),
                          "+f"(c[ti][tj][2]), "+f"(c[ti][tj][3])
                        : "r"(afr[cur][ti][0]), "r"(afr[cur][ti][1]),
                          "r"(afr[cur][ti][2]), "r"(afr[cur][ti][3]),
                          "r"(bfr[cur][tj][0]), "r"(bfr[cur][tj][1]));
                }
        }
    }

    // epilogue
    #pragma unroll
    for (int ti = 0; ti < 4; ti++) {
        int r0 = bm + wr * 64 + ti * 16 + g;
        #pragma unroll
        for (int tj = 0; tj < 8; tj++) {
            int cn = bn + wc * 64 + tj * 8 + t * 2;
            float v[4] = {c[ti][tj][0], c[ti][tj][1], c[ti][tj][2], c[ti][tj][3]};
            if (BIAS) {
                float b0 = bias[cn], b1 = bias[cn + 1];
                v[0] += b0; v[1] += b1; v[2] += b0; v[3] += b1;
            }
            if (GELU) {
                #pragma unroll
                for (int q = 0; q < 4; q++)
                    v[q] = 0.5f * v[q] * (1.0f + erff(v[q] * 0.70710678118654752f));
            }
            if (RES) {
                float2 r0v = *(const float2*)&res[(size_t)r0 * Nout + cn];
                float2 r1v = *(const float2*)&res[(size_t)(r0 + 8) * Nout + cn];
                v[0] += r0v.x; v[1] += r0v.y; v[2] += r1v.x; v[3] += r1v.y;
            }
            if (OUTH) {
                *(__half2*)&outh[(size_t)r0 * Nout + cn]       = __floats2half2_rn(v[0], v[1]);
                *(__half2*)&outh[(size_t)(r0 + 8) * Nout + cn] = __floats2half2_rn(v[2], v[3]);
            } else {
                *(float2*)&outf[(size_t)r0 * Nout + cn]       = make_float2(v[0], v[1]);
                *(float2*)&outf[(size_t)(r0 + 8) * Nout + cn] = make_float2(v[2], v[3]);
            }
        }
    }
}

// ---------------- fused attention: scores + top-16 + softmax -> fp16 ----------------
// Q staged in smem as fp32 (pre-scaled); K staged as packed half2 (2 MACs per 4B LDS).
#define KS_STRIDE 33   // half2 stride per row: conflict-free lane mapping
__global__ void attn_topk_kernel(const __half* __restrict__ qk, __half* __restrict__ a) {
    int bh = blockIdx.x;
    int b = bh / H_, h = bh % H_;
    extern __shared__ float sm[];
    float*    Qs  = sm;                         // [196][64] fp32, pre-scaled
    uint32_t* Ks2 = (uint32_t*)(sm + N_ * HD_); // [196][33] half2

    int tid = threadIdx.x, lane = tid & 31, warp = tid >> 5;
    int nwarp = blockDim.x >> 5;

    const __half* base = qk + (size_t)b * N_ * (2 * C_);
    for (int e = tid; e < N_ * 32; e += blockDim.x) {
        int n = e >> 5, dp = e & 31;
        __half2 qh = *(const __half2*)&base[(size_t)n * (2 * C_) + h * HD_ + dp * 2];
        float2 qf = __half22float2(qh);
        Qs[n * HD_ + dp * 2]     = qf.x * SCALE_;
        Qs[n * HD_ + dp * 2 + 1] = qf.y * SCALE_;
        Ks2[n * KS_STRIDE + dp] = *(const uint32_t*)&base[(size_t)n * (2 * C_) + C_ + h * HD_ + dp * 2];
    }
    __syncthreads();

    for (int i = warp; i < N_; i += nwarp) {
        int jj[7];
        float sloc[7];
        #pragma unroll
        for (int t2 = 0; t2 < 7; t2++) {
            int j = lane + 32 * t2;
            jj[t2] = (j < N_) ? j * KS_STRIDE : 0;
            sloc[t2] = 0.f;
        }
        const float2* qrow2 = (const float2*)(Qs + i * HD_);
        #pragma unroll 4
        for (int dp = 0; dp < 32; dp++) {
            float2 qf = qrow2[dp];
            #pragma unroll
            for (int t2 = 0; t2 < 7; t2++) {
                uint32_t kp = Ks2[jj[t2] + dp];
                float2 kf = __half22float2(*(__half2*)&kp);
                sloc[t2] += qf.x * kf.x + qf.y * kf.y;
            }
        }
        #pragma unroll
        for (int t2 = 0; t2 < 7; t2++)
            if (lane + 32 * t2 >= N_) sloc[t2] = -INFINITY;

        float top[16];
        #pragma unroll
        for (int sel = 0; sel < TOPK_; sel++) {
            float m = sloc[0]; int tl = 0;
            #pragma unroll
            for (int t2 = 1; t2 < 7; t2++)
                if (sloc[t2] > m) { m = sloc[t2]; tl = t2; }
            int key = (lane << 3) | tl;
            #pragma unroll
            for (int o = 16; o > 0; o >>= 1) {
                float om = __shfl_xor_sync(0xffffffffu, m, o);
                int ok   = __shfl_xor_sync(0xffffffffu, key, o);
                if (om > m || (om == m && ok < key)) { m = om; key = ok; }
            }
            top[sel] = m;
            if (lane == (key >> 3)) sloc[key & 7] = -INFINITY;
        }

        float ssum = 0.f;
        #pragma unroll
        for (int t2 = 0; t2 < TOPK_; t2++) ssum += expf(top[t2] - top[0]);
        if (lane < TOPK_) {
            float val = expf(top[lane] - top[0]) / ssum;
            a[((size_t)(b * N_ + i)) * (H_ * TOPK_) + h * TOPK_ + lane] = __float2half(val);
        }
    }
}

// ---------------- launch ----------------
extern "C" void kernel_launch(void* const* d_in, const int* in_sizes, int n_in,
                              void* d_out, int out_size) {
    const float* x      = (const float*)d_in[0];
    const float* n1g    = (const float*)d_in[1];
    const float* n1b    = (const float*)d_in[2];
    const float* qk_w   = (const float*)d_in[3];
    const float* proj_w = (const float*)d_in[4];
    const float* proj_b = (const float*)d_in[5];
    const float* n2g    = (const float*)d_in[6];
    const float* n2b    = (const float*)d_in[7];
    const float* fc1_w  = (const float*)d_in[8];
    const float* fc1_b  = (const float*)d_in[9];
    const float* fc2_w  = (const float*)d_in[10];
    const float* fc2_b  = (const float*)d_in[11];
    float* out = (float*)d_out;

    __half *h_h, *qk_h, *a_h, *hid_h, *qkw_h, *pw_h, *f1w_h, *f2w_h;
    float *x1;
    cudaGetSymbolAddress((void**)&h_h,   g_h_h);
    cudaGetSymbolAddress((void**)&qk_h,  g_qk_h);
    cudaGetSymbolAddress((void**)&a_h,   g_a_h);
    cudaGetSymbolAddress((void**)&x1,    g_x1);
    cudaGetSymbolAddress((void**)&hid_h, g_hid_h);
    cudaGetSymbolAddress((void**)&qkw_h, g_qkw_h);
    cudaGetSymbolAddress((void**)&pw_h,  g_pw_h);
    cudaGetSymbolAddress((void**)&f1w_h, g_f1w_h);
    cudaGetSymbolAddress((void**)&f2w_h, g_f2w_h);

    cudaFuncSetAttribute((const void*)gemm_h<false,false,false,true>, cudaFuncAttributeMaxDynamicSharedMemorySize, SMEM_SZ);
    cudaFuncSetAttribute((const void*)gemm_h<true,false,true,false>,  cudaFuncAttributeMaxDynamicSharedMemorySize, SMEM_SZ);
    cudaFuncSetAttribute((const void*)gemm_h<true,true,false,true>,   cudaFuncAttributeMaxDynamicSharedMemorySize, SMEM_SZ);

    // merged weight conversions (fp32 -> fp16)
    {
        int n0 = 2 * C_ * C_;        // 1179648
        int n1 = C_ * H_ * TOPK_;    // 147456
        int n2 = HID_ * C_;          // 2359296
        int n3 = C_ * HID_;          // 2359296
        int total = n0 + n1 + n2 + n3;
        cvt4_kernel<<<(total / 4 + 255) / 256, 256>>>(qk_w, qkw_h, n0,
                                                      proj_w, pw_h, n1,
                                                      fc1_w, f1w_h, n2,
                                                      fc2_w, f2w_h, n3);
    }

    // 1. LN1 -> fp16
    ln_kernel<<<M_, 192>>>(x, n1g, n1b, h_h);

    // 2. qk = h @ qk_w^T   [M, 1536], K=768 (fp16 out)
    gemm_h<false, false, false, true><<<dim3((2 * C_) / 128, M_ / 128), 128, SMEM_SZ>>>(
        h_h, qkw_h, nullptr, nullptr, nullptr, qk_h, 2 * C_, C_);

    // 3. attention -> a fp16 [M, 192]
    int smem = (N_ * HD_) * (int)sizeof(float) + N_ * KS_STRIDE * 4;  // ~76 KB
    cudaFuncSetAttribute(attn_topk_kernel, cudaFuncAttributeMaxDynamicSharedMemorySize, smem);
    attn_topk_kernel<<<B_ * H_, 256, smem>>>(qk_h, a_h);

    // 4. x1 = x + a @ proj_w^T + proj_b   [M, 768], K=192
    gemm_h<true, false, true, false><<<dim3(C_ / 128, M_ / 128), 128, SMEM_SZ>>>(
        a_h, pw_h, proj_b, x, x1, nullptr, C_, H_ * TOPK_);

    // 5. LN2 -> fp16
    ln_kernel<<<M_, 192>>>(x1, n2g, n2b, h_h);

    // 6. hid = gelu(h @ fc1_w^T + fc1_b) -> fp16 [M, 3072], K=768
    gemm_h<true, true, false, true><<<dim3(HID_ / 128, M_ / 128), 128, SMEM_SZ>>>(
        h_h, f1w_h, fc1_b, nullptr, nullptr, hid_h, HID_, C_);

    // 7. out = x1 + hid @ fc2_w^T + fc2_b  [M, 768], K=3072
    gemm_h<true, false, true, false><<<dim3(C_ / 128, M_ / 128), 128, SMEM_SZ>>>(
        hid_h, f2w_h, fc2_b, x1, out, nullptr, C_, HID_);
}

// round 12
// speedup vs baseline: 1.7151x; 1.4447x over previous
#include <cuda_runtime.h>
#include <cuda_fp16.h>
#include <math.h>
#include <stdint.h>

#define B_   64
#define N_   196
#define C_   768
#define H_   12
#define HD_  64
#define TOPK_ 16
#define HID_ 3072
#define M_   (B_ * N_)          // 12544
#define SCALE_ 0.125f
#define EPS_ 1e-5f

// ---------------- scratch (device globals) ----------------
__device__ __half g_h_h  [(size_t)M_ * C_];
__device__ __half g_qk_h [(size_t)M_ * 2 * C_];
__device__ __half g_a_h  [(size_t)M_ * H_ * TOPK_];
__device__ float  g_x1   [(size_t)M_ * C_];
__device__ __half g_hid_h[(size_t)M_ * HID_];
// fp16 weights
__device__ __half g_qkw_h[(size_t)2 * C_ * C_];
__device__ __half g_pw_h [(size_t)C_ * H_ * TOPK_];
__device__ __half g_f1w_h[(size_t)HID_ * C_];
__device__ __half g_f2w_h[(size_t)C_ * HID_];

// ---------------- helpers ----------------
__device__ __forceinline__ void cp_async16(void* smem, const void* gmem) {
    uint32_t s = (uint32_t)__cvta_generic_to_shared(smem);
    asm volatile("cp.async.cg.shared.global [%0], [%1], 16;\n" :: "r"(s), "l"(gmem));
}
__device__ __forceinline__ void cp_commit() { asm volatile("cp.async.commit_group;\n"); }
template <int Np>
__device__ __forceinline__ void cp_wait() { asm volatile("cp.async.wait_group %0;\n" :: "n"(Np) : "memory"); }
__device__ __forceinline__ void ldsm4(uint32_t& r0, uint32_t& r1, uint32_t& r2, uint32_t& r3,
                                      uint32_t addr) {
    asm volatile("ldmatrix.sync.aligned.m8n8.x4.shared.b16 {%0,%1,%2,%3}, [%4];\n"
                 : "=r"(r0), "=r"(r1), "=r"(r2), "=r"(r3) : "r"(addr));
}

// ---------------- merged weight fp32 -> fp16 (float4 vectorized) ----------------
__global__ void cvt4_kernel(const float* __restrict__ s0, __half* __restrict__ d0, int n0,
                            const float* __restrict__ s1, __half* __restrict__ d1, int n1,
                            const float* __restrict__ s2, __half* __restrict__ d2, int n2,
                            const float* __restrict__ s3, __half* __restrict__ d3, int n3) {
    int i = (blockIdx.x * 256 + threadIdx.x) * 4;
    const float* s; __half* d; int off;
    if (i < n0)                { s = s0; d = d0; off = 0; }
    else if (i < n0 + n1)      { s = s1; d = d1; off = n0; }
    else if (i < n0 + n1 + n2) { s = s2; d = d2; off = n0 + n1; }
    else if (i < n0 + n1 + n2 + n3) { s = s3; d = d3; off = n0 + n1 + n2; }
    else return;
    int j = i - off;
    float4 v = *(const float4*)&s[j];
    __half2 h0 = __floats2half2_rn(v.x, v.y);
    __half2 h1 = __floats2half2_rn(v.z, v.w);
    *(uint2*)&d[j] = make_uint2(*(uint32_t*)&h0, *(uint32_t*)&h1);
}

// ---------------- LayerNorm -> fp16 (float4 vectorized, 192 threads) ----------------
__global__ void ln_kernel(const float* __restrict__ x, const float* __restrict__ g,
                          const float* __restrict__ b, __half* __restrict__ out) {
    int row = blockIdx.x;
    const float4* xr = (const float4*)(x + (size_t)row * C_);
    int tid = threadIdx.x, lane = tid & 31, warp = tid >> 5;   // 192 threads, 6 warps

    float4 v = xr[tid];
    float s  = v.x + v.y + v.z + v.w;
    float s2 = v.x * v.x + v.y * v.y + v.z * v.z + v.w * v.w;
    #pragma unroll
    for (int o = 16; o > 0; o >>= 1) {
        s  += __shfl_xor_sync(0xffffffffu, s,  o);
        s2 += __shfl_xor_sync(0xffffffffu, s2, o);
    }
    __shared__ float shs[6], shs2[6], sh_mu, sh_inv;
    if (lane == 0) { shs[warp] = s; shs2[warp] = s2; }
    __syncthreads();
    if (tid == 0) {
        float ts = 0.f, ts2 = 0.f;
        #pragma unroll
        for (int w = 0; w < 6; w++) { ts += shs[w]; ts2 += shs2[w]; }
        float mu = ts / C_;
        sh_mu = mu; sh_inv = rsqrtf(ts2 / C_ - mu * mu + EPS_);
    }
    __syncthreads();
    float mu = sh_mu, inv = sh_inv;
    float4 gv = ((const float4*)g)[tid];
    float4 bv = ((const float4*)b)[tid];
    float o0 = (v.x - mu) * inv * gv.x + bv.x;
    float o1 = (v.y - mu) * inv * gv.y + bv.y;
    float o2 = (v.z - mu) * inv * gv.z + bv.z;
    float o3 = (v.w - mu) * inv * gv.w + bv.w;
    __half2 h0 = __floats2half2_rn(o0, o1);
    __half2 h1 = __floats2half2_rn(o2, o3);
    *(uint2*)&out[(size_t)row * C_ + tid * 4] = make_uint2(*(uint32_t*)&h0, *(uint32_t*)&h1);
}

// ---------------- FP16 mma.sync GEMM (frag double-buffered) ----------------
#define STG_B 32768               // (128+128) rows * 128 B
#define NSTG  3
#define SMEM_SZ (NSTG * STG_B)

template <bool BIAS, bool GELU, bool RES, bool OUTH>
__global__ __launch_bounds__(128, 2) void gemm_h(
        const __half* __restrict__ A, const __half* __restrict__ W,
        const float* __restrict__ bias, const float* __restrict__ res,
        float* __restrict__ outf, __half* __restrict__ outh, int Nout, int K) {
    extern __shared__ char smem[];
    uint32_t sb = (uint32_t)__cvta_generic_to_shared(smem);

    int tid = threadIdx.x;
    int lane = tid & 31, wid = tid >> 5;
    int wr = wid >> 1, wc = wid & 1;
    int g = lane >> 2, t = lane & 3;
    int grp = lane >> 3, l7 = lane & 7;
    int bm = blockIdx.y * 128, bn = blockIdx.x * 128;

    const __half* Ablk = A + (size_t)bm * K;
    const __half* Wblk = W + (size_t)bn * K;

    float c[4][8][4];
    #pragma unroll
    for (int i = 0; i < 4; i++)
        #pragma unroll
        for (int j = 0; j < 8; j++)
            #pragma unroll
            for (int r = 0; r < 4; r++) c[i][j][r] = 0.f;

    int lrow0 = tid >> 3;
    int lseg  = tid & 7;
    uint32_t lcol = (uint32_t)((lseg ^ (lrow0 & 7)) << 4);
    auto load_stage = [&](int slot, int k0) {
        char* sbase = smem + slot * STG_B;
        #pragma unroll
        for (int i = 0; i < 16; i++) {
            int row = lrow0 + (i & 7) * 16;
            int isB = i >> 3;
            const __half* src = (isB ? Wblk : Ablk) + (size_t)row * K + k0 + lseg * 8;
            char* dst = sbase + isB * 16384 + row * 128 + lcol;
            cp_async16(dst, src);
        }
        cp_commit();
    };

    int NK = K / 64;
    load_stage(0, 0);
    load_stage(1, 64);

    int rowoffA = (grp & 1) * 8, segoffA = grp >> 1;
    int rowoffB = (grp >> 1) * 8, segoffB = grp & 1;

    uint32_t afr[2][4][4], bfr[2][8][2];

    auto load_frags = [&](int j, int buf, uint32_t sA, uint32_t sB) {
        #pragma unroll
        for (int ti = 0; ti < 4; ti++) {
            int row = wr * 64 + ti * 16 + rowoffA + l7;
            uint32_t addr = sA + (row << 7) + (((2 * j + segoffA) ^ (row & 7)) << 4);
            ldsm4(afr[buf][ti][0], afr[buf][ti][1], afr[buf][ti][2], afr[buf][ti][3], addr);
        }
        #pragma unroll
        for (int tp = 0; tp < 4; tp++) {
            int row = wc * 64 + tp * 16 + rowoffB + l7;
            uint32_t addr = sB + (row << 7) + (((2 * j + segoffB) ^ (row & 7)) << 4);
            uint32_t r0, r1, r2, r3;
            ldsm4(r0, r1, r2, r3, addr);
            bfr[buf][2 * tp][0] = r0;     bfr[buf][2 * tp][1] = r1;
            bfr[buf][2 * tp + 1][0] = r2; bfr[buf][2 * tp + 1][1] = r3;
        }
    };

    for (int kc = 0; kc < NK; kc++) {
        int slot = kc % NSTG;
        cp_wait<1>();
        __syncthreads();

        if (kc + 2 < NK) load_stage((kc + 2) % NSTG, (kc + 2) * 64);
        else cp_commit();

        uint32_t sA = sb + slot * STG_B;
        uint32_t sB = sA + 16384;

        load_frags(0, 0, sA, sB);
        #pragma unroll
        for (int j = 0; j < 4; j++) {
            int cur = j & 1;
            if (j < 3) load_frags(j + 1, cur ^ 1, sA, sB);
            #pragma unroll
            for (int ti = 0; ti < 4; ti++)
                #pragma unroll
                for (int tj = 0; tj < 8; tj++) {
                    asm volatile(
                        "mma.sync.aligned.m16n8k16.row.col.f32.f16.f16.f32 "
                        "{%0,%1,%2,%3}, {%4,%5,%6,%7}, {%8,%9}, {%0,%1,%2,%3};\n"
                        : "+f"(c[ti][tj][0]), "+f"(c[ti][tj][1]),
                          "+f"(c[ti][tj][2]), "+f"(c[ti][tj][3])
                        : "r"(afr[cur][ti][0]), "r"(afr[cur][ti][1]),
                          "r"(afr[cur][ti][2]), "r"(afr[cur][ti][3]),
                          "r"(bfr[cur][tj][0]), "r"(bfr[cur][tj][1]));
                }
        }
    }

    // epilogue
    #pragma unroll
    for (int ti = 0; ti < 4; ti++) {
        int r0 = bm + wr * 64 + ti * 16 + g;
        #pragma unroll
        for (int tj = 0; tj < 8; tj++) {
            int cn = bn + wc * 64 + tj * 8 + t * 2;
            float v[4] = {c[ti][tj][0], c[ti][tj][1], c[ti][tj][2], c[ti][tj][3]};
            if (BIAS) {
                float b0 = bias[cn], b1 = bias[cn + 1];
                v[0] += b0; v[1] += b1; v[2] += b0; v[3] += b1;
            }
            if (GELU) {
                #pragma unroll
                for (int q = 0; q < 4; q++)
                    v[q] = 0.5f * v[q] * (1.0f + erff(v[q] * 0.70710678118654752f));
            }
            if (RES) {
                float2 r0v = *(const float2*)&res[(size_t)r0 * Nout + cn];
                float2 r1v = *(const float2*)&res[(size_t)(r0 + 8) * Nout + cn];
                v[0] += r0v.x; v[1] += r0v.y; v[2] += r1v.x; v[3] += r1v.y;
            }
            if (OUTH) {
                *(__half2*)&outh[(size_t)r0 * Nout + cn]       = __floats2half2_rn(v[0], v[1]);
                *(__half2*)&outh[(size_t)(r0 + 8) * Nout + cn] = __floats2half2_rn(v[2], v[3]);
            } else {
                *(float2*)&outf[(size_t)r0 * Nout + cn]       = make_float2(v[0], v[1]);
                *(float2*)&outf[(size_t)(r0 + 8) * Nout + cn] = make_float2(v[2], v[3]);
            }
        }
    }
}

// ---------------- fused attention v2: half2 scoring + packed-uint top-16 ----------------
// Q (pre-scaled) and K both packed half2 in smem (~50 KB -> 4 blocks/SM).
// Top-16 via ordered-uint keys: one SHFL + one UMAX per butterfly step.
#define KS_STRIDE 33
__global__ __launch_bounds__(256) void attn_topk_kernel(const __half* __restrict__ qk,
                                                        __half* __restrict__ a) {
    int bh = blockIdx.x;
    int b = bh / H_, h = bh % H_;
    extern __shared__ uint32_t sm2[];
    uint32_t* Qs2 = sm2;              // [196][32] half2, pre-scaled
    uint32_t* Ks2 = sm2 + N_ * 32;    // [196][33] half2 (padded)

    int tid = threadIdx.x, lane = tid & 31, warp = tid >> 5;

    const __half* base = qk + (size_t)b * N_ * (2 * C_);
    const __half2 sc = __float2half2_rn(SCALE_);
    for (int e = tid; e < N_ * 32; e += 256) {
        int n = e >> 5, dp = e & 31;
        __half2 qh = *(const __half2*)&base[(size_t)n * (2 * C_) + h * HD_ + dp * 2];
        qh = __hmul2(qh, sc);
        Qs2[n * 32 + dp] = *(uint32_t*)&qh;
        Ks2[n * KS_STRIDE + dp] = *(const uint32_t*)&base[(size_t)n * (2 * C_) + C_ + h * HD_ + dp * 2];
    }
    __syncthreads();

    for (int i = warp; i < N_; i += 8) {
        int jj[7];
        #pragma unroll
        for (int t = 0; t < 7; t++) {
            int j = lane + 32 * t;
            jj[t] = (j < N_) ? j * KS_STRIDE : 0;
        }
        __half2 acc0[7], acc1[7];
        #pragma unroll
        for (int t = 0; t < 7; t++) {
            acc0[t] = __float2half2_rn(0.f);
            acc1[t] = __float2half2_rn(0.f);
        }
        const uint32_t* qrow = Qs2 + i * 32;
        #pragma unroll 4
        for (int dp = 0; dp < 32; dp += 2) {
            uint32_t q0u = qrow[dp], q1u = qrow[dp + 1];
            __half2 q0 = *(__half2*)&q0u, q1 = *(__half2*)&q1u;
            #pragma unroll
            for (int t = 0; t < 7; t++) {
                uint32_t k0 = Ks2[jj[t] + dp];
                uint32_t k1 = Ks2[jj[t] + dp + 1];
                acc0[t] = __hfma2(q0, *(__half2*)&k0, acc0[t]);
                acc1[t] = __hfma2(q1, *(__half2*)&k1, acc1[t]);
            }
        }
        // pack scores into ordered uints with (lane<<3|slot) id in low 8 bits
        uint32_t p[7];
        #pragma unroll
        for (int t = 0; t < 7; t++) {
            float2 f0 = __half22float2(acc0[t]);
            float2 f1 = __half22float2(acc1[t]);
            float s = (f0.x + f0.y) + (f1.x + f1.y);
            uint32_t ub = __float_as_uint(s);
            ub = (s >= 0.f) ? (ub | 0x80000000u) : ~ub;
            p[t] = (lane + 32 * t < N_) ? ((ub & 0xFFFFFF00u) | (uint32_t)(lane << 3) | (uint32_t)t) : 0u;
        }
        float top[16];
        #pragma unroll
        for (int sel = 0; sel < TOPK_; sel++) {
            uint32_t m = p[0];
            #pragma unroll
            for (int t = 1; t < 7; t++) m = (p[t] > m) ? p[t] : m;
            #pragma unroll
            for (int o = 16; o > 0; o >>= 1) {
                uint32_t om = __shfl_xor_sync(0xffffffffu, m, o);
                m = (om > m) ? om : m;
            }
            uint32_t ub = m & 0xFFFFFF00u;
            top[sel] = (ub & 0x80000000u) ? __uint_as_float(ub & 0x7FFFFFFFu)
                                          : __uint_as_float(~ub);
            if (lane == (int)((m >> 3) & 31u)) {
                int sl = (int)(m & 7u);
                #pragma unroll
                for (int t = 0; t < 7; t++) if (t == sl) p[t] = 0u;
            }
        }
        float ssum = 0.f;
        #pragma unroll
        for (int t = 0; t < TOPK_; t++) ssum += expf(top[t] - top[0]);
        if (lane < TOPK_) {
            float val = expf(top[lane] - top[0]) / ssum;
            a[((size_t)(b * N_ + i)) * (H_ * TOPK_) + h * TOPK_ + lane] = __float2half(val);
        }
    }
}

// ---------------- launch ----------------
extern "C" void kernel_launch(void* const* d_in, const int* in_sizes, int n_in,
                              void* d_out, int out_size) {
    const float* x      = (const float*)d_in[0];
    const float* n1g    = (const float*)d_in[1];
    const float* n1b    = (const float*)d_in[2];
    const float* qk_w   = (const float*)d_in[3];
    const float* proj_w = (const float*)d_in[4];
    const float* proj_b = (const float*)d_in[5];
    const float* n2g    = (const float*)d_in[6];
    const float* n2b    = (const float*)d_in[7];
    const float* fc1_w  = (const float*)d_in[8];
    const float* fc1_b  = (const float*)d_in[9];
    const float* fc2_w  = (const float*)d_in[10];
    const float* fc2_b  = (const float*)d_in[11];
    float* out = (float*)d_out;

    __half *h_h, *qk_h, *a_h, *hid_h, *qkw_h, *pw_h, *f1w_h, *f2w_h;
    float *x1;
    cudaGetSymbolAddress((void**)&h_h,   g_h_h);
    cudaGetSymbolAddress((void**)&qk_h,  g_qk_h);
    cudaGetSymbolAddress((void**)&a_h,   g_a_h);
    cudaGetSymbolAddress((void**)&x1,    g_x1);
    cudaGetSymbolAddress((void**)&hid_h, g_hid_h);
    cudaGetSymbolAddress((void**)&qkw_h, g_qkw_h);
    cudaGetSymbolAddress((void**)&pw_h,  g_pw_h);
    cudaGetSymbolAddress((void**)&f1w_h, g_f1w_h);
    cudaGetSymbolAddress((void**)&f2w_h, g_f2w_h);

    cudaFuncSetAttribute((const void*)gemm_h<false,false,false,true>, cudaFuncAttributeMaxDynamicSharedMemorySize, SMEM_SZ);
    cudaFuncSetAttribute((const void*)gemm_h<true,false,true,false>,  cudaFuncAttributeMaxDynamicSharedMemorySize, SMEM_SZ);
    cudaFuncSetAttribute((const void*)gemm_h<true,true,false,true>,   cudaFuncAttributeMaxDynamicSharedMemorySize, SMEM_SZ);

    // merged weight conversions (fp32 -> fp16)
    {
        int n0 = 2 * C_ * C_;
        int n1 = C_ * H_ * TOPK_;
        int n2 = HID_ * C_;
        int n3 = C_ * HID_;
        int total = n0 + n1 + n2 + n3;
        cvt4_kernel<<<(total / 4 + 255) / 256, 256>>>(qk_w, qkw_h, n0,
                                                      proj_w, pw_h, n1,
                                                      fc1_w, f1w_h, n2,
                                                      fc2_w, f2w_h, n3);
    }

    // 1. LN1 -> fp16
    ln_kernel<<<M_, 192>>>(x, n1g, n1b, h_h);

    // 2. qk = h @ qk_w^T   [M, 1536], K=768 (fp16 out)
    gemm_h<false, false, false, true><<<dim3((2 * C_) / 128, M_ / 128), 128, SMEM_SZ>>>(
        h_h, qkw_h, nullptr, nullptr, nullptr, qk_h, 2 * C_, C_);

    // 3. attention -> a fp16 [M, 192]
    int smem = N_ * 32 * 4 + N_ * KS_STRIDE * 4;  // 50960 B -> 4 blocks/SM
    cudaFuncSetAttribute(attn_topk_kernel, cudaFuncAttributeMaxDynamicSharedMemorySize, smem);
    attn_topk_kernel<<<B_ * H_, 256, smem>>>(qk_h, a_h);

    // 4. x1 = x + a @ proj_w^T + proj_b   [M, 768], K=192
    gemm_h<true, false, true, false><<<dim3(C_ / 128, M_ / 128), 128, SMEM_SZ>>>(
        a_h, pw_h, proj_b, x, x1, nullptr, C_, H_ * TOPK_);

    // 5. LN2 -> fp16
    ln_kernel<<<M_, 192>>>(x1, n2g, n2b, h_h);

    // 6. hid = gelu(h @ fc1_w^T + fc1_b) -> fp16 [M, 3072], K=768
    gemm_h<true, true, false, true><<<dim3(HID_ / 128, M_ / 128), 128, SMEM_SZ>>>(
        h_h, f1w_h, fc1_b, nullptr, nullptr, hid_h, HID_, C_);

    // 7. out = x1 + hid @ fc2_w^T + fc2_b  [M, 768], K=3072
    gemm_h<true, false, true, false><<<dim3(C_ / 128, M_ / 128), 128, SMEM_SZ>>>(
        hid_h, f2w_h, fc2_b, x1, out, nullptr, C_, HID_);
}